// round 3
// baseline (speedup 1.0000x reference)
#include <cuda_runtime.h>
#include <math.h>

#define W 512
#define H 512
#define HW (H * W)
#define TWO_PI 6.283185307179586f

#define NMAX 5000
#define TILES_X 32
#define TILES_Y 32
#define NTILES (TILES_X * TILES_Y)
#define CAP 1024          // max gaussians per tile in global list
#define SCAP 512          // smem staging chunk

// SoA per-gaussian params (written by bin, read by render)
__device__ float4 g_p0[NMAX];        // cx, cy, 0.5*A, 0.5*C
__device__ float4 g_p1[NMAX];        // B, op*c0, op*c1, op*c2
__device__ float  g_tm[NMAX];        // tmax = log(255*op); sigma in [0, tmax) contributes
__device__ int    g_tilecount[NTILES];   // zero-init BSS; render re-zeroes each replay
__device__ int    g_tilelist[NTILES * CAP];

__global__ void bin_kernel(const float* __restrict__ xyz,
                           const float* __restrict__ scaling,
                           const float* __restrict__ rot,
                           const float* __restrict__ feat,
                           const float* __restrict__ opac,
                           int n) {
    int g = blockIdx.x * blockDim.x + threadIdx.x;
    if (g >= n) return;

    float2 xy = ((const float2*)xyz)[g];
    float2 sc = ((const float2*)scaling)[g];
    float mx = tanhf(xy.x);
    float my = tanhf(xy.y);
    float sx = fabsf(sc.x + 0.5f);
    float sy = fabsf(sc.y + 0.5f);
    float theta = (1.0f / (1.0f + expf(-rot[g]))) * TWO_PI;

    float cx = 0.5f * ((mx + 1.0f) * (float)W - 1.0f);
    float cy = 0.5f * ((my + 1.0f) * (float)H - 1.0f);

    float sth, cth;
    sincosf(theta, &sth, &cth);
    float sx2 = sx * sx;
    float sy2 = sy * sy;
    float a = cth * cth * sx2 + sth * sth * sy2;
    float b = cth * sth * (sx2 - sy2);
    float c = sth * sth * sx2 + cth * cth * sy2;
    float det = a * c - b * b;
    if (!(det > 0.0f)) return;
    float inv_det = 1.0f / fmaxf(det, 1e-12f);
    float A = c * inv_det;
    float B = -b * inv_det;
    float C = a * inv_det;

    float op = opac[g];
    float tmax = logf(op * 255.0f);     // alpha > 1/255  <=>  sigma < tmax
    if (!(tmax > 0.0f)) return;

    float rx = sqrtf(2.0f * tmax * a) + 1.0f;   // exact test re-rejects margin
    float ry = sqrtf(2.0f * tmax * c) + 1.0f;

    int x0 = max(0, (int)ceilf(cx - rx));
    int x1 = min(W - 1, (int)floorf(cx + rx));
    int y0 = max(0, (int)ceilf(cy - ry));
    int y1 = min(H - 1, (int)floorf(cy + ry));
    if (x1 < x0 || y1 < y0) return;

    g_p0[g] = make_float4(cx, cy, 0.5f * A, 0.5f * C);
    g_p1[g] = make_float4(B, op * feat[3 * g], op * feat[3 * g + 1], op * feat[3 * g + 2]);
    g_tm[g] = tmax;

    int tx0 = x0 >> 4, tx1 = x1 >> 4;
    int ty0 = y0 >> 4, ty1 = y1 >> 4;
    for (int ty = ty0; ty <= ty1; ty++) {
        for (int tx = tx0; tx <= tx1; tx++) {
            int t = ty * TILES_X + tx;
            int s = atomicAdd(&g_tilecount[t], 1);
            if (s < CAP) g_tilelist[t * CAP + s] = g;
        }
    }
}

__global__ __launch_bounds__(256) void render_kernel(float* __restrict__ out) {
    __shared__ float4 sq0[SCAP];
    __shared__ float4 sq1[SCAP];
    __shared__ float  stm[SCAP];

    int tile = blockIdx.x;
    int tx = tile & (TILES_X - 1);
    int ty = tile >> 5;
    int tid = threadIdx.x;
    int px = (tx << 4) + (tid & 15);
    int py = (ty << 4) + (tid >> 4);
    float fx = (float)px;
    float fy = (float)py;

    int cnt = min(g_tilecount[tile], CAP);
    const int* __restrict__ list = &g_tilelist[tile * CAP];

    float acc0 = 0.0f, acc1 = 0.0f, acc2 = 0.0f;

    int base = 0;
    do {
        int m = min(SCAP, cnt - base);      // may be 0 for empty tile
        if (base) __syncthreads();
        for (int i = tid; i < m; i += 256) {
            int gi = list[base + i];
            sq0[i] = g_p0[gi];
            sq1[i] = g_p1[gi];
            stm[i] = g_tm[gi];
        }
        int mp = (m + 7) & ~7;              // pad to unroll factor with duds
        if (tid >= m && tid < mp) {
            sq0[tid] = make_float4(0.f, 0.f, 0.f, 0.f);
            sq1[tid] = make_float4(0.f, 0.f, 0.f, 0.f);
            stm[tid] = -1.0f;               // predicate always false
        }
        __syncthreads();

        for (int e = 0; e < mp; e += 8) {
            #pragma unroll
            for (int u = 0; u < 8; u++) {
                float4 q0 = sq0[e + u];     // cx, cy, hA, hC
                float4 q1 = sq1[e + u];     // B, oc0, oc1, oc2
                float  tm = stm[e + u];
                float dx = q0.x - fx;
                float dy = q0.y - fy;
                float sigma = fmaf(q0.z, dx * dx,
                              fmaf(q0.w, dy * dy, q1.x * (dx * dy)));
                float w = __expf(-sigma);
                w = ((sigma >= 0.0f) && (sigma < tm)) ? w : 0.0f;
                acc0 = fmaf(w, q1.y, acc0);
                acc1 = fmaf(w, q1.z, acc1);
                acc2 = fmaf(w, q1.w, acc2);
            }
        }
        base += SCAP;
    } while (base < cnt);

    int pix = py * W + px;
    out[pix]          = fminf(fmaxf(acc0, 0.0f), 1.0f);
    out[HW + pix]     = fminf(fmaxf(acc1, 0.0f), 1.0f);
    out[2 * HW + pix] = fminf(fmaxf(acc2, 0.0f), 1.0f);

    // leave counter zeroed for next graph replay
    if (tid == 0) g_tilecount[tile] = 0;
}

extern "C" void kernel_launch(void* const* d_in, const int* in_sizes, int n_in,
                              void* d_out, int out_size) {
    const float* xyz     = (const float*)d_in[0];  // (N,2)
    const float* scaling = (const float*)d_in[1];  // (N,2)
    const float* rot     = (const float*)d_in[2];  // (N,1)
    const float* feat    = (const float*)d_in[3];  // (N,3)
    const float* opac    = (const float*)d_in[4];  // (N,1)
    float* out = (float*)d_out;                     // (1,3,512,512)

    int n = in_sizes[0] / 2;

    bin_kernel<<<(n + 255) / 256, 256>>>(xyz, scaling, rot, feat, opac, n);
    render_kernel<<<NTILES, 256>>>(out);
}